// round 2
// baseline (speedup 1.0000x reference)
#include <cuda_runtime.h>
#include <cuda_bf16.h>
#include <mma.h>
#include <math.h>

using namespace nvcuda;

// Problem constants
constexpr int S  = 97;
constexpr int Bb = 256;
constexpr int W  = 1024;
constexpr int H  = 16;
constexpr int HD = 64;
constexpr long MROWS = (long)S * Bb;        // 24832 = 194*128
constexpr long MW    = MROWS * W;           // 25,427,968 elements
constexpr int  GK    = 1024;                // K dim of every GEMM

// ---------------- device scratch ----------------
__device__ float g_q[MW];
__device__ float g_k[MW];
__device__ float g_v[MW];
__device__ __nv_bfloat16 g_ahi[MW], g_alo[MW];
__device__ __nv_bfloat16 g_bhi[MW], g_blo[MW];
__device__ __nv_bfloat16 g_chi[MW], g_clo[MW];
__device__ __nv_bfloat16 g_dhi[MW], g_dlo[MW];
__device__ __nv_bfloat16 g_whi[8L*1024*1024], g_wlo[8L*1024*1024];

// ---------------- helpers ----------------
__device__ __forceinline__ void split2(float v, __nv_bfloat16& h, __nv_bfloat16& l) {
    h = __float2bfloat16(v);
    l = __float2bfloat16(v - __bfloat162float(h));
}

// ---------------- weight/input split ----------------
__global__ void split_kernel(const float* __restrict__ x,
                             __nv_bfloat16* __restrict__ hi,
                             __nv_bfloat16* __restrict__ lo, int n) {
    int i = blockIdx.x * 256 + threadIdx.x;
    if (i >= n) return;
    __nv_bfloat16 h, l;
    split2(x[i], h, l);
    hi[i] = h; lo[i] = l;
}

// ---------------- 3-term bf16 split GEMM with fused epilogue ----------------
// C[m,n] = sum_k A[m,k] * Wt[n,k], A = Ahi+Alo, Wt = Bhi+Blo (drop lo*lo)
// Epilogue modes:
//   EPI_OUT:   out_f[m,n]  = acc + bias[n]                       (float)
//   EPI_SPLIT: (hi,lo)[m,n] = split(acc + bias[n])               (bf16 pair)
//   EPI_ROT:   bias, then rotary over column pairs, then split   (bf16 pair)
constexpr int BM = 128, BN = 128, BK = 32;
constexpr int LDSM = 40;                       // smem leading dim (bf16 elems)
constexpr int STAGE_E = 4 * 128 * LDSM;        // elements per stage (4 tiles)
constexpr int LDC = 132;                       // epilogue float staging ld
constexpr int GEMM_SMEM = 2 * STAGE_E * 2;     // 81920 bytes >= 128*LDC*4 (67584)

enum { EPI_OUT = 0, EPI_SPLIT = 1, EPI_ROT = 2 };

__device__ __forceinline__ void cp16(unsigned dst, const void* src) {
    asm volatile("cp.async.cg.shared.global [%0], [%1], 16;\n" :: "r"(dst), "l"(src));
}

template<int MODE>
__global__ __launch_bounds__(256, 2)
void gemm3_kernel(const __nv_bfloat16* __restrict__ Ahi, const __nv_bfloat16* __restrict__ Alo,
                  const __nv_bfloat16* __restrict__ Bhi, const __nv_bfloat16* __restrict__ Blo,
                  const float* __restrict__ bias,
                  float* __restrict__ Cf,
                  __nv_bfloat16* __restrict__ Ohi, __nv_bfloat16* __restrict__ Olo) {
    extern __shared__ __nv_bfloat16 smem_g[];
    const int tid = threadIdx.x;
    const int wid = tid >> 5;
    const int wm = wid >> 2;       // 0..1
    const int wn = wid & 3;        // 0..3
    const long bm = (long)blockIdx.y * BM;
    const long bn = (long)blockIdx.x * BN;

    wmma::fragment<wmma::accumulator, 16, 16, 16, float> acc[4][2];
#pragma unroll
    for (int i = 0; i < 4; i++)
#pragma unroll
        for (int j = 0; j < 2; j++) wmma::fill_fragment(acc[i][j], 0.0f);

    const int r0 = tid >> 2;            // 0..63
    const int c0 = (tid & 3) << 3;      // 0,8,16,24
    unsigned sbase = (unsigned)__cvta_generic_to_shared(smem_g);

    auto issue = [&](int kt, int st) {
        unsigned s0 = sbase + (unsigned)st * (STAGE_E * 2);
        const int gc = kt * BK + c0;
#pragma unroll
        for (int t = 0; t < 2; t++) {
            int r = r0 + t * 64;
            unsigned so = s0 + (unsigned)(r * LDSM + c0) * 2;
            cp16(so,                      Ahi + (bm + r) * GK + gc);
            cp16(so + 1 * 128 * LDSM * 2, Alo + (bm + r) * GK + gc);
            cp16(so + 2 * 128 * LDSM * 2, Bhi + (bn + r) * GK + gc);
            cp16(so + 3 * 128 * LDSM * 2, Blo + (bn + r) * GK + gc);
        }
        asm volatile("cp.async.commit_group;\n");
    };

    issue(0, 0);
    const int NT = GK / BK;   // 32
    for (int kt = 0; kt < NT; ++kt) {
        int cur = kt & 1;
        if (kt + 1 < NT) {
            issue(kt + 1, cur ^ 1);
            asm volatile("cp.async.wait_group 1;\n");
        } else {
            asm volatile("cp.async.wait_group 0;\n");
        }
        __syncthreads();
        const __nv_bfloat16* sAhi = smem_g + cur * STAGE_E;
        const __nv_bfloat16* sAlo = sAhi + 128 * LDSM;
        const __nv_bfloat16* sBhi = sAlo + 128 * LDSM;
        const __nv_bfloat16* sBlo = sBhi + 128 * LDSM;
#pragma unroll
        for (int kk = 0; kk < BK; kk += 16) {
            wmma::fragment<wmma::matrix_b, 16, 16, 16, __nv_bfloat16, wmma::col_major> fbh[2], fbl[2];
#pragma unroll
            for (int j = 0; j < 2; j++) {
                wmma::load_matrix_sync(fbh[j], sBhi + (wn * 32 + j * 16) * LDSM + kk, LDSM);
                wmma::load_matrix_sync(fbl[j], sBlo + (wn * 32 + j * 16) * LDSM + kk, LDSM);
            }
#pragma unroll
            for (int i = 0; i < 4; i++) {
                wmma::fragment<wmma::matrix_a, 16, 16, 16, __nv_bfloat16, wmma::row_major> fah, fal;
                wmma::load_matrix_sync(fah, sAhi + (wm * 64 + i * 16) * LDSM + kk, LDSM);
                wmma::load_matrix_sync(fal, sAlo + (wm * 64 + i * 16) * LDSM + kk, LDSM);
#pragma unroll
                for (int j = 0; j < 2; j++) {
                    wmma::mma_sync(acc[i][j], fah, fbh[j], acc[i][j]);
                    wmma::mma_sync(acc[i][j], fah, fbl[j], acc[i][j]);
                    wmma::mma_sync(acc[i][j], fal, fbh[j], acc[i][j]);
                }
            }
        }
        __syncthreads();
    }

    // ---- fused epilogue: stage tile through smem (reuses pipeline buffers) ----
    float* st = reinterpret_cast<float*>(smem_g);
#pragma unroll
    for (int i = 0; i < 4; i++)
#pragma unroll
        for (int j = 0; j < 2; j++)
            wmma::store_matrix_sync(st + (wm * 64 + i * 16) * LDC + wn * 32 + j * 16,
                                    acc[i][j], LDC, wmma::mem_row_major);
    __syncthreads();

    // 128 rows x 64 col-pairs = 8192 pairs; 32 per thread
#pragma unroll 4
    for (int it = 0; it < 32; ++it) {
        int p = it * 256 + tid;
        int row = p >> 6;
        int col = (p & 63) << 1;           // even column within tile
        int gcol = (int)bn + col;          // global column (0..1023)
        float x0 = st[row * LDC + col]     + bias[gcol];
        float x1 = st[row * LDC + col + 1] + bias[gcol + 1];
        size_t g = (size_t)(bm + row) * 1024 + gcol;
        if (MODE == EPI_OUT) {
            Cf[g]     = x0;
            Cf[g + 1] = x1;
        } else if (MODE == EPI_SPLIT) {
            __nv_bfloat16 h, l;
            split2(x0, h, l); Ohi[g] = h;     Olo[g] = l;
            split2(x1, h, l); Ohi[g + 1] = h; Olo[g + 1] = l;
        } else {
            // rotary: pair (gcol, gcol+1), seq position s = row_index / B
            int sp = (int)((bm + row) >> 8);   // Bb = 256
            float freq = exp2f((float)gcol * (-13.287712379549449f / 1024.0f));
            float sn, cs;
            sincosf((float)sp * freq, &sn, &cs);
            float oe = x0 * cs - x1 * sn;
            float oo = x0 * sn + x1 * cs;
            __nv_bfloat16 h, l;
            split2(oe, h, l); Ohi[g] = h;     Olo[g] = l;
            split2(oo, h, l); Ohi[g + 1] = h; Olo[g + 1] = l;
        }
    }
}

// ---------------- attention ----------------
// one block per (b,h): smem-staged Q,K,V; fp32 SIMT scores + softmax + P@V
// emits bf16 hi/lo split directly (feeds next GEMM)
constexpr int KLD = 65;     // conflict-free strided K reads
constexpr int PLD = 100;
constexpr int Q_OFF = 0;                        // 104*64 rows (overread pad)
constexpr int K_OFF = 104 * 64;                 // 6656
constexpr int V_OFF = K_OFF + S * KLD;          // +6305
constexpr int P_OFF = V_OFF + S * 64;           // +6208
constexpr int ATTN_ELEMS = P_OFF + 104 * PLD;   // +10400 = 29569
constexpr int ATTN_SMEM = ATTN_ELEMS * 4;       // 118276 bytes

__global__ void attn_kernel(const float* __restrict__ q, const float* __restrict__ k,
                            const float* __restrict__ v, const float* __restrict__ mask,
                            __nv_bfloat16* __restrict__ ohi, __nv_bfloat16* __restrict__ olo) {
    extern __shared__ float sm[];
    float* Qs = sm + Q_OFF;
    float* Ks = sm + K_OFF;
    float* Vs = sm + V_OFF;
    float* Ps = sm + P_OFF;
    const int tid = threadIdx.x, w = tid >> 5, l = tid & 31;
    const int b = blockIdx.x / H, h = blockIdx.x % H;
    const size_t base = (size_t)b * W + (size_t)h * HD;

    for (int i = tid; i < S * HD; i += 256) {
        int s = i >> 6, d = i & 63;
        size_t g = (size_t)s * Bb * W + base + d;
        Qs[s * 64 + d]  = q[g];
        Ks[s * KLD + d] = k[g];
        Vs[s * 64 + d]  = v[g];
    }
    __syncthreads();

    // scores: warp w handles rows i = w + 8r (r<13); lane l handles j = jb*32+l
    {
        float acc[13][4];
#pragma unroll
        for (int r = 0; r < 13; r++)
#pragma unroll
            for (int jb = 0; jb < 4; jb++) acc[r][jb] = 0.0f;

        for (int d = 0; d < HD; ++d) {
            float k0 = Ks[l * KLD + d];
            float k1 = Ks[(l + 32) * KLD + d];
            float k2 = Ks[(l + 64) * KLD + d];
            float k3 = (l == 0) ? Ks[96 * KLD + d] : 0.0f;
#pragma unroll
            for (int r = 0; r < 13; r++) {
                float qv = Qs[(w + 8 * r) * 64 + d];   // padded overread for invalid rows
                acc[r][0] += qv * k0;
                acc[r][1] += qv * k1;
                acc[r][2] += qv * k2;
                acc[r][3] += qv * k3;
            }
        }
        const float scale = 0.125f;   // 1/sqrt(64)
#pragma unroll
        for (int r = 0; r < 13; r++) {
            int i = w + 8 * r;
            if (i < S) {
#pragma unroll
                for (int jb = 0; jb < 4; jb++) {
                    int j = jb * 32 + l;
                    if (j < S) Ps[i * PLD + j] = acc[r][jb] * scale + mask[i * S + j];
                }
            }
        }
    }
    __syncthreads();

    // softmax per row
    for (int r = 0; r < 13; r++) {
        int i = w + 8 * r;
        if (i >= S) break;   // warp-uniform
        float x[4];
#pragma unroll
        for (int jb = 0; jb < 4; jb++) {
            int j = jb * 32 + l;
            x[jb] = (j < S) ? Ps[i * PLD + j] : -1e30f;
        }
        float m = fmaxf(fmaxf(x[0], x[1]), fmaxf(x[2], x[3]));
#pragma unroll
        for (int off = 16; off; off >>= 1) m = fmaxf(m, __shfl_xor_sync(0xffffffffu, m, off));
        float e[4], ssum = 0.0f;
#pragma unroll
        for (int jb = 0; jb < 4; jb++) {
            int j = jb * 32 + l;
            e[jb] = (j < S) ? expf(x[jb] - m) : 0.0f;
            ssum += e[jb];
        }
#pragma unroll
        for (int off = 16; off; off >>= 1) ssum += __shfl_xor_sync(0xffffffffu, ssum, off);
        float inv = 1.0f / ssum;
#pragma unroll
        for (int jb = 0; jb < 4; jb++) {
            int j = jb * 32 + l;
            if (j < S) Ps[i * PLD + j] = e[jb] * inv;
        }
    }
    __syncthreads();

    // O = P @ V : lane l owns d = l and d = l+32; write bf16 hi/lo split
    {
        float a0[13], a1[13];
#pragma unroll
        for (int r = 0; r < 13; r++) { a0[r] = 0.0f; a1[r] = 0.0f; }
        for (int j = 0; j < S; ++j) {
            float v0 = Vs[j * 64 + l];
            float v1 = Vs[j * 64 + l + 32];
#pragma unroll
            for (int r = 0; r < 13; r++) {
                float p = Ps[(w + 8 * r) * PLD + j];   // padded overread for invalid rows
                a0[r] += p * v0;
                a1[r] += p * v1;
            }
        }
#pragma unroll
        for (int r = 0; r < 13; r++) {
            int i = w + 8 * r;
            if (i < S) {
                size_t g = (size_t)i * Bb * W + base + l;
                __nv_bfloat16 hh, ll;
                split2(a0[r], hh, ll); ohi[g] = hh;      olo[g] = ll;
                split2(a1[r], hh, ll); ohi[g + 32] = hh; olo[g + 32] = ll;
            }
        }
    }
}

// ---------------- launch ----------------
extern "C" void kernel_launch(void* const* d_in, const int* in_sizes, int n_in,
                              void* d_out, int out_size) {
    const float* tensor = (const float*)d_in[0];
    const float* mask   = (const float*)d_in[1];
    const float* q_w    = (const float*)d_in[2];
    const float* q_b    = (const float*)d_in[3];
    const float* k_w    = (const float*)d_in[4];
    const float* k_b    = (const float*)d_in[5];
    const float* v_w    = (const float*)d_in[6];
    const float* v_b    = (const float*)d_in[7];
    const float* in_w   = (const float*)d_in[8];
    const float* in_b   = (const float*)d_in[9];
    const float* mo_w   = (const float*)d_in[10];
    const float* mo_b   = (const float*)d_in[11];
    const float* o_w    = (const float*)d_in[12];
    const float* o_b    = (const float*)d_in[13];
    float* out = (float*)d_out;

    void* p;
    cudaGetSymbolAddress(&p, g_q);   float* qbuf = (float*)p;
    cudaGetSymbolAddress(&p, g_k);   float* kbuf = (float*)p;
    cudaGetSymbolAddress(&p, g_v);   float* vbuf = (float*)p;
    cudaGetSymbolAddress(&p, g_ahi); __nv_bfloat16* ahi = (__nv_bfloat16*)p;
    cudaGetSymbolAddress(&p, g_alo); __nv_bfloat16* alo = (__nv_bfloat16*)p;
    cudaGetSymbolAddress(&p, g_bhi); __nv_bfloat16* bhi = (__nv_bfloat16*)p;
    cudaGetSymbolAddress(&p, g_blo); __nv_bfloat16* blo = (__nv_bfloat16*)p;
    cudaGetSymbolAddress(&p, g_chi); __nv_bfloat16* chi = (__nv_bfloat16*)p;
    cudaGetSymbolAddress(&p, g_clo); __nv_bfloat16* clo = (__nv_bfloat16*)p;
    cudaGetSymbolAddress(&p, g_dhi); __nv_bfloat16* dhi = (__nv_bfloat16*)p;
    cudaGetSymbolAddress(&p, g_dlo); __nv_bfloat16* dlo = (__nv_bfloat16*)p;
    cudaGetSymbolAddress(&p, g_whi); __nv_bfloat16* whi = (__nv_bfloat16*)p;
    cudaGetSymbolAddress(&p, g_wlo); __nv_bfloat16* wlo = (__nv_bfloat16*)p;

    cudaFuncSetAttribute(gemm3_kernel<EPI_OUT>,   cudaFuncAttributeMaxDynamicSharedMemorySize, GEMM_SMEM);
    cudaFuncSetAttribute(gemm3_kernel<EPI_SPLIT>, cudaFuncAttributeMaxDynamicSharedMemorySize, GEMM_SMEM);
    cudaFuncSetAttribute(gemm3_kernel<EPI_ROT>,   cudaFuncAttributeMaxDynamicSharedMemorySize, GEMM_SMEM);
    cudaFuncSetAttribute(attn_kernel,             cudaFuncAttributeMaxDynamicSharedMemorySize, ATTN_SMEM);

    const int T = 256;
    const int WW = 1024 * 1024;
    const int gW = (WW + T - 1) / T;
    const int nM = (int)MW;
    const int gM = (nM + T - 1) / T;

    // split weights -> bf16 hi/lo (slots: 0=q_w 1=k_w 2=v_w 3..5=in_proj 6=mha_out 7=out)
    split_kernel<<<gW, T>>>(q_w,  whi,            wlo,            WW);
    split_kernel<<<gW, T>>>(k_w,  whi + 1 * WW,   wlo + 1 * WW,   WW);
    split_kernel<<<gW, T>>>(v_w,  whi + 2 * WW,   wlo + 2 * WW,   WW);
    split_kernel<<<3 * gW, T>>>(in_w, whi + 3 * WW, wlo + 3 * WW, 3 * WW);
    split_kernel<<<gW, T>>>(mo_w, whi + 6 * WW,   wlo + 6 * WW,   WW);
    split_kernel<<<gW, T>>>(o_w,  whi + 7LL * WW, wlo + 7LL * WW, WW);

    // split input -> ahi/alo
    split_kernel<<<gM, T>>>(tensor, ahi, alo, nM);

    dim3 gg(8, 194);
    // q/k/v projections with fused bias (+rotary for q,k) + split
    gemm3_kernel<EPI_ROT>  <<<gg, 256, GEMM_SMEM>>>(ahi, alo, whi,          wlo,          q_b, nullptr, bhi, blo);
    gemm3_kernel<EPI_ROT>  <<<gg, 256, GEMM_SMEM>>>(ahi, alo, whi + 1 * WW, wlo + 1 * WW, k_b, nullptr, chi, clo);
    gemm3_kernel<EPI_SPLIT><<<gg, 256, GEMM_SMEM>>>(ahi, alo, whi + 2 * WW, wlo + 2 * WW, v_b, nullptr, dhi, dlo);

    // in_proj with fused bias -> float q/k/v for attention
    gemm3_kernel<EPI_OUT>  <<<gg, 256, GEMM_SMEM>>>(bhi, blo, whi + 3 * WW, wlo + 3 * WW, in_b,        qbuf, nullptr, nullptr);
    gemm3_kernel<EPI_OUT>  <<<gg, 256, GEMM_SMEM>>>(chi, clo, whi + 4 * WW, wlo + 4 * WW, in_b + 1024, kbuf, nullptr, nullptr);
    gemm3_kernel<EPI_OUT>  <<<gg, 256, GEMM_SMEM>>>(dhi, dlo, whi + 5 * WW, wlo + 5 * WW, in_b + 2048, vbuf, nullptr, nullptr);

    // attention -> bf16 hi/lo split directly
    attn_kernel<<<Bb * H, 256, ATTN_SMEM>>>(qbuf, kbuf, vbuf, mask, ahi, alo);

    // mha_out projection with fused bias + split
    gemm3_kernel<EPI_SPLIT><<<gg, 256, GEMM_SMEM>>>(ahi, alo, whi + 6 * WW, wlo + 6 * WW, mo_b, nullptr, bhi, blo);

    // final projection with fused bias -> d_out
    gemm3_kernel<EPI_OUT>  <<<gg, 256, GEMM_SMEM>>>(bhi, blo, whi + 7LL * WW, wlo + 7LL * WW, o_b, out, nullptr, nullptr);
}

// round 4
// speedup vs baseline: 1.1203x; 1.1203x over previous
#include <cuda_runtime.h>
#include <cuda_bf16.h>
#include <mma.h>
#include <math.h>

using namespace nvcuda;

// Problem constants
constexpr int S  = 97;
constexpr int Bb = 256;
constexpr int W  = 1024;
constexpr int H  = 16;
constexpr int HD = 64;
constexpr long MROWS = (long)S * Bb;        // 24832 = 194*128
constexpr long MW    = MROWS * W;           // 25,427,968 elements
constexpr int  GK    = 1024;                // K dim of every GEMM

// ---------------- device scratch ----------------
__device__ float g_q[MW];
__device__ float g_k[MW];
__device__ float g_v[MW];
__device__ __nv_bfloat16 g_ahi[MW], g_alo[MW];
__device__ __nv_bfloat16 g_bhi[MW], g_blo[MW];
__device__ __nv_bfloat16 g_chi[MW], g_clo[MW];
__device__ __nv_bfloat16 g_dhi[MW], g_dlo[MW];
__device__ __nv_bfloat16 g_whi[8L*1024*1024], g_wlo[8L*1024*1024];

// ---------------- helpers ----------------
__device__ __forceinline__ void split2(float v, __nv_bfloat16& h, __nv_bfloat16& l) {
    h = __float2bfloat16(v);
    l = __float2bfloat16(v - __bfloat162float(h));
}

// ---------------- weight/input split ----------------
__global__ void split_kernel(const float* __restrict__ x,
                             __nv_bfloat16* __restrict__ hi,
                             __nv_bfloat16* __restrict__ lo, int n) {
    int i = blockIdx.x * 256 + threadIdx.x;
    if (i >= n) return;
    __nv_bfloat16 h, l;
    split2(x[i], h, l);
    hi[i] = h; lo[i] = l;
}

// ---------------- 3-term bf16 split GEMM with fused epilogue ----------------
// C[m,n] = sum_k A[m,k] * Wt[n,k], A = Ahi+Alo, Wt = Bhi+Blo (drop lo*lo)
// 4 warps, warp tile 64x64 (3:1 mma:ldsm ratio), 2-stage cp.async.
// Epilogue modes:
//   EPI_OUT:   out_f[m,n]  = acc + bias[n]                       (float)
//   EPI_SPLIT: (hi,lo)[m,n] = split(acc + bias[n])               (bf16 pair)
//   EPI_ROT:   bias, then rotary over column pairs, then split   (bf16 pair)
constexpr int BM = 128, BN = 128, BK = 32;
constexpr int LDSM = 40;                       // smem leading dim (bf16 elems)
constexpr int STAGE_E = 4 * 128 * LDSM;        // elements per stage (4 tiles)
constexpr int LDC = 132;                       // epilogue float staging ld
constexpr int GEMM_SMEM = 2 * STAGE_E * 2;     // 81920 bytes >= 128*LDC*4 (67584)

enum { EPI_OUT = 0, EPI_SPLIT = 1, EPI_ROT = 2 };

__device__ __forceinline__ void cp16(unsigned dst, const void* src) {
    asm volatile("cp.async.cg.shared.global [%0], [%1], 16;\n" :: "r"(dst), "l"(src));
}

template<int MODE>
__global__ __launch_bounds__(128, 2)
void gemm3_kernel(const __nv_bfloat16* __restrict__ Ahi, const __nv_bfloat16* __restrict__ Alo,
                  const __nv_bfloat16* __restrict__ Bhi, const __nv_bfloat16* __restrict__ Blo,
                  const float* __restrict__ bias,
                  float* __restrict__ Cf,
                  __nv_bfloat16* __restrict__ Ohi, __nv_bfloat16* __restrict__ Olo) {
    extern __shared__ __nv_bfloat16 smem_g[];
    const int tid = threadIdx.x;
    const int wid = tid >> 5;
    const int wm = wid >> 1;       // 0..1
    const int wn = wid & 1;        // 0..1
    const long bm = (long)blockIdx.y * BM;
    const long bn = (long)blockIdx.x * BN;

    wmma::fragment<wmma::accumulator, 16, 16, 16, float> acc[4][4];
#pragma unroll
    for (int i = 0; i < 4; i++)
#pragma unroll
        for (int j = 0; j < 4; j++) wmma::fill_fragment(acc[i][j], 0.0f);

    const int r0 = tid >> 2;            // 0..31
    const int c0 = (tid & 3) << 3;      // 0,8,16,24
    unsigned sbase = (unsigned)__cvta_generic_to_shared(smem_g);

    auto issue = [&](int kt, int st) {
        unsigned s0 = sbase + (unsigned)st * (STAGE_E * 2);
        const int gc = kt * BK + c0;
#pragma unroll
        for (int t = 0; t < 4; t++) {
            int r = r0 + t * 32;
            unsigned so = s0 + (unsigned)(r * LDSM + c0) * 2;
            cp16(so,                      Ahi + (bm + r) * GK + gc);
            cp16(so + 1 * 128 * LDSM * 2, Alo + (bm + r) * GK + gc);
            cp16(so + 2 * 128 * LDSM * 2, Bhi + (bn + r) * GK + gc);
            cp16(so + 3 * 128 * LDSM * 2, Blo + (bn + r) * GK + gc);
        }
        asm volatile("cp.async.commit_group;\n");
    };

    issue(0, 0);
    const int NT = GK / BK;   // 32
    for (int kt = 0; kt < NT; ++kt) {
        int cur = kt & 1;
        if (kt + 1 < NT) {
            issue(kt + 1, cur ^ 1);
            asm volatile("cp.async.wait_group 1;\n");
        } else {
            asm volatile("cp.async.wait_group 0;\n");
        }
        __syncthreads();
        const __nv_bfloat16* sAhi = smem_g + cur * STAGE_E;
        const __nv_bfloat16* sAlo = sAhi + 128 * LDSM;
        const __nv_bfloat16* sBhi = sAlo + 128 * LDSM;
        const __nv_bfloat16* sBlo = sBhi + 128 * LDSM;
#pragma unroll
        for (int kk = 0; kk < BK; kk += 16) {
            wmma::fragment<wmma::matrix_a, 16, 16, 16, __nv_bfloat16, wmma::row_major> fah[4], fal[4];
#pragma unroll
            for (int i = 0; i < 4; i++) {
                wmma::load_matrix_sync(fah[i], sAhi + (wm * 64 + i * 16) * LDSM + kk, LDSM);
                wmma::load_matrix_sync(fal[i], sAlo + (wm * 64 + i * 16) * LDSM + kk, LDSM);
            }
#pragma unroll
            for (int j = 0; j < 4; j++) {
                wmma::fragment<wmma::matrix_b, 16, 16, 16, __nv_bfloat16, wmma::col_major> fbh, fbl;
                wmma::load_matrix_sync(fbh, sBhi + (wn * 64 + j * 16) * LDSM + kk, LDSM);
                wmma::load_matrix_sync(fbl, sBlo + (wn * 64 + j * 16) * LDSM + kk, LDSM);
#pragma unroll
                for (int i = 0; i < 4; i++) {
                    wmma::mma_sync(acc[i][j], fah[i], fbh, acc[i][j]);
                    wmma::mma_sync(acc[i][j], fah[i], fbl, acc[i][j]);
                    wmma::mma_sync(acc[i][j], fal[i], fbh, acc[i][j]);
                }
            }
        }
        __syncthreads();
    }

    // ---- fused epilogue: stage tile through smem (reuses pipeline buffers) ----
    float* st = reinterpret_cast<float*>(smem_g);
#pragma unroll
    for (int i = 0; i < 4; i++)
#pragma unroll
        for (int j = 0; j < 4; j++)
            wmma::store_matrix_sync(st + (wm * 64 + i * 16) * LDC + wn * 64 + j * 16,
                                    acc[i][j], LDC, wmma::mem_row_major);
    __syncthreads();

    // 128 rows x 64 col-pairs = 8192 pairs; 64 per thread (128 threads)
#pragma unroll 4
    for (int it = 0; it < 64; ++it) {
        int p = it * 128 + tid;
        int row = p >> 6;
        int col = (p & 63) << 1;           // even column within tile
        int gcol = (int)bn + col;          // global column (0..1023)
        float x0 = st[row * LDC + col]     + bias[gcol];
        float x1 = st[row * LDC + col + 1] + bias[gcol + 1];
        size_t g = (size_t)(bm + row) * 1024 + gcol;
        if (MODE == EPI_OUT) {
            Cf[g]     = x0;
            Cf[g + 1] = x1;
        } else if (MODE == EPI_SPLIT) {
            __nv_bfloat16 h, l;
            split2(x0, h, l); Ohi[g] = h;     Olo[g] = l;
            split2(x1, h, l); Ohi[g + 1] = h; Olo[g + 1] = l;
        } else {
            // rotary: pair (gcol, gcol+1), seq position s = row_index / B
            int sp = (int)((bm + row) >> 8);   // Bb = 256
            float freq = exp2f((float)gcol * (-13.287712379549449f / 1024.0f));
            float sn, cs;
            sincosf((float)sp * freq, &sn, &cs);
            float oe = x0 * cs - x1 * sn;
            float oo = x0 * sn + x1 * cs;
            __nv_bfloat16 h, l;
            split2(oe, h, l); Ohi[g] = h;     Olo[g] = l;
            split2(oo, h, l); Ohi[g + 1] = h; Olo[g + 1] = l;
        }
    }
}

// ---------------- attention ----------------
// one block per (b,h): smem-staged Q,K,V; fp32 SIMT scores + softmax + P@V
// emits bf16 hi/lo split directly (feeds next GEMM)
constexpr int KLD = 65;     // conflict-free strided K reads
constexpr int PLD = 100;
constexpr int Q_OFF = 0;                        // 104*64 rows (overread pad)
constexpr int K_OFF = 104 * 64;                 // 6656
constexpr int V_OFF = K_OFF + S * KLD;          // +6305
constexpr int P_OFF = V_OFF + S * 64;           // +6208
constexpr int ATTN_ELEMS = P_OFF + 104 * PLD;   // +10400 = 29569
constexpr int ATTN_SMEM = ATTN_ELEMS * 4;       // 118276 bytes

__global__ void attn_kernel(const float* __restrict__ q, const float* __restrict__ k,
                            const float* __restrict__ v, const float* __restrict__ mask,
                            __nv_bfloat16* __restrict__ ohi, __nv_bfloat16* __restrict__ olo) {
    extern __shared__ float sm[];
    float* Qs = sm + Q_OFF;
    float* Ks = sm + K_OFF;
    float* Vs = sm + V_OFF;
    float* Ps = sm + P_OFF;
    const int tid = threadIdx.x, w = tid >> 5, l = tid & 31;
    const int b = blockIdx.x / H, h = blockIdx.x % H;
    const size_t base = (size_t)b * W + (size_t)h * HD;

    for (int i = tid; i < S * HD; i += 256) {
        int s = i >> 6, d = i & 63;
        size_t g = (size_t)s * Bb * W + base + d;
        Qs[s * 64 + d]  = q[g];
        Ks[s * KLD + d] = k[g];
        Vs[s * 64 + d]  = v[g];
    }
    __syncthreads();

    // scores: warp w handles rows i = w + 8r (r<13); lane l handles j = jb*32+l
    {
        float acc[13][4];
#pragma unroll
        for (int r = 0; r < 13; r++)
#pragma unroll
            for (int jb = 0; jb < 4; jb++) acc[r][jb] = 0.0f;

        for (int d = 0; d < HD; ++d) {
            float k0 = Ks[l * KLD + d];
            float k1 = Ks[(l + 32) * KLD + d];
            float k2 = Ks[(l + 64) * KLD + d];
            float k3 = (l == 0) ? Ks[96 * KLD + d] : 0.0f;
#pragma unroll
            for (int r = 0; r < 13; r++) {
                float qv = Qs[(w + 8 * r) * 64 + d];   // padded overread for invalid rows
                acc[r][0] += qv * k0;
                acc[r][1] += qv * k1;
                acc[r][2] += qv * k2;
                acc[r][3] += qv * k3;
            }
        }
        const float scale = 0.125f;   // 1/sqrt(64)
#pragma unroll
        for (int r = 0; r < 13; r++) {
            int i = w + 8 * r;
            if (i < S) {
#pragma unroll
                for (int jb = 0; jb < 4; jb++) {
                    int j = jb * 32 + l;
                    if (j < S) Ps[i * PLD + j] = acc[r][jb] * scale + mask[i * S + j];
                }
            }
        }
    }
    __syncthreads();

    // softmax per row
    for (int r = 0; r < 13; r++) {
        int i = w + 8 * r;
        if (i >= S) break;   // warp-uniform
        float x[4];
#pragma unroll
        for (int jb = 0; jb < 4; jb++) {
            int j = jb * 32 + l;
            x[jb] = (j < S) ? Ps[i * PLD + j] : -1e30f;
        }
        float m = fmaxf(fmaxf(x[0], x[1]), fmaxf(x[2], x[3]));
#pragma unroll
        for (int off = 16; off; off >>= 1) m = fmaxf(m, __shfl_xor_sync(0xffffffffu, m, off));
        float e[4], ssum = 0.0f;
#pragma unroll
        for (int jb = 0; jb < 4; jb++) {
            int j = jb * 32 + l;
            e[jb] = (j < S) ? expf(x[jb] - m) : 0.0f;
            ssum += e[jb];
        }
#pragma unroll
        for (int off = 16; off; off >>= 1) ssum += __shfl_xor_sync(0xffffffffu, ssum, off);
        float inv = 1.0f / ssum;
#pragma unroll
        for (int jb = 0; jb < 4; jb++) {
            int j = jb * 32 + l;
            if (j < S) Ps[i * PLD + j] = e[jb] * inv;
        }
    }
    __syncthreads();

    // O = P @ V : lane l owns d = l and d = l+32; write bf16 hi/lo split
    {
        float a0[13], a1[13];
#pragma unroll
        for (int r = 0; r < 13; r++) { a0[r] = 0.0f; a1[r] = 0.0f; }
        for (int j = 0; j < S; ++j) {
            float v0 = Vs[j * 64 + l];
            float v1 = Vs[j * 64 + l + 32];
#pragma unroll
            for (int r = 0; r < 13; r++) {
                float p = Ps[(w + 8 * r) * PLD + j];   // padded overread for invalid rows
                a0[r] += p * v0;
                a1[r] += p * v1;
            }
        }
#pragma unroll
        for (int r = 0; r < 13; r++) {
            int i = w + 8 * r;
            if (i < S) {
                size_t g = (size_t)i * Bb * W + base + l;
                __nv_bfloat16 hh, ll;
                split2(a0[r], hh, ll); ohi[g] = hh;      olo[g] = ll;
                split2(a1[r], hh, ll); ohi[g + 32] = hh; olo[g + 32] = ll;
            }
        }
    }
}

// ---------------- launch ----------------
extern "C" void kernel_launch(void* const* d_in, const int* in_sizes, int n_in,
                              void* d_out, int out_size) {
    const float* tensor = (const float*)d_in[0];
    const float* mask   = (const float*)d_in[1];
    const float* q_w    = (const float*)d_in[2];
    const float* q_b    = (const float*)d_in[3];
    const float* k_w    = (const float*)d_in[4];
    const float* k_b    = (const float*)d_in[5];
    const float* v_w    = (const float*)d_in[6];
    const float* v_b    = (const float*)d_in[7];
    const float* in_w   = (const float*)d_in[8];
    const float* in_b   = (const float*)d_in[9];
    const float* mo_w   = (const float*)d_in[10];
    const float* mo_b   = (const float*)d_in[11];
    const float* o_w    = (const float*)d_in[12];
    const float* o_b    = (const float*)d_in[13];
    float* out = (float*)d_out;

    void* p;
    cudaGetSymbolAddress(&p, g_q);   float* qbuf = (float*)p;
    cudaGetSymbolAddress(&p, g_k);   float* kbuf = (float*)p;
    cudaGetSymbolAddress(&p, g_v);   float* vbuf = (float*)p;
    cudaGetSymbolAddress(&p, g_ahi); __nv_bfloat16* ahi = (__nv_bfloat16*)p;
    cudaGetSymbolAddress(&p, g_alo); __nv_bfloat16* alo = (__nv_bfloat16*)p;
    cudaGetSymbolAddress(&p, g_bhi); __nv_bfloat16* bhi = (__nv_bfloat16*)p;
    cudaGetSymbolAddress(&p, g_blo); __nv_bfloat16* blo = (__nv_bfloat16*)p;
    cudaGetSymbolAddress(&p, g_chi); __nv_bfloat16* chi = (__nv_bfloat16*)p;
    cudaGetSymbolAddress(&p, g_clo); __nv_bfloat16* clo = (__nv_bfloat16*)p;
    cudaGetSymbolAddress(&p, g_dhi); __nv_bfloat16* dhi = (__nv_bfloat16*)p;
    cudaGetSymbolAddress(&p, g_dlo); __nv_bfloat16* dlo = (__nv_bfloat16*)p;
    cudaGetSymbolAddress(&p, g_whi); __nv_bfloat16* whi = (__nv_bfloat16*)p;
    cudaGetSymbolAddress(&p, g_wlo); __nv_bfloat16* wlo = (__nv_bfloat16*)p;

    cudaFuncSetAttribute(gemm3_kernel<EPI_OUT>,   cudaFuncAttributeMaxDynamicSharedMemorySize, GEMM_SMEM);
    cudaFuncSetAttribute(gemm3_kernel<EPI_SPLIT>, cudaFuncAttributeMaxDynamicSharedMemorySize, GEMM_SMEM);
    cudaFuncSetAttribute(gemm3_kernel<EPI_ROT>,   cudaFuncAttributeMaxDynamicSharedMemorySize, GEMM_SMEM);
    cudaFuncSetAttribute(attn_kernel,             cudaFuncAttributeMaxDynamicSharedMemorySize, ATTN_SMEM);

    const int T = 256;
    const int WW = 1024 * 1024;
    const int gW = (WW + T - 1) / T;
    const int nM = (int)MW;
    const int gM = (nM + T - 1) / T;

    // split weights -> bf16 hi/lo (slots: 0=q_w 1=k_w 2=v_w 3..5=in_proj 6=mha_out 7=out)
    split_kernel<<<gW, T>>>(q_w,  whi,            wlo,            WW);
    split_kernel<<<gW, T>>>(k_w,  whi + 1 * WW,   wlo + 1 * WW,   WW);
    split_kernel<<<gW, T>>>(v_w,  whi + 2 * WW,   wlo + 2 * WW,   WW);
    split_kernel<<<3 * gW, T>>>(in_w, whi + 3 * WW, wlo + 3 * WW, 3 * WW);
    split_kernel<<<gW, T>>>(mo_w, whi + 6 * WW,   wlo + 6 * WW,   WW);
    split_kernel<<<gW, T>>>(o_w,  whi + 7LL * WW, wlo + 7LL * WW, WW);

    // split input -> ahi/alo
    split_kernel<<<gM, T>>>(tensor, ahi, alo, nM);

    dim3 gg(8, 194);
    // q/k/v projections with fused bias (+rotary for q,k) + split
    gemm3_kernel<EPI_ROT>  <<<gg, 128, GEMM_SMEM>>>(ahi, alo, whi,          wlo,          q_b, nullptr, bhi, blo);
    gemm3_kernel<EPI_ROT>  <<<gg, 128, GEMM_SMEM>>>(ahi, alo, whi + 1 * WW, wlo + 1 * WW, k_b, nullptr, chi, clo);
    gemm3_kernel<EPI_SPLIT><<<gg, 128, GEMM_SMEM>>>(ahi, alo, whi + 2 * WW, wlo + 2 * WW, v_b, nullptr, dhi, dlo);

    // in_proj with fused bias -> float q/k/v for attention
    gemm3_kernel<EPI_OUT>  <<<gg, 128, GEMM_SMEM>>>(bhi, blo, whi + 3 * WW, wlo + 3 * WW, in_b,        qbuf, nullptr, nullptr);
    gemm3_kernel<EPI_OUT>  <<<gg, 128, GEMM_SMEM>>>(chi, clo, whi + 4 * WW, wlo + 4 * WW, in_b + 1024, kbuf, nullptr, nullptr);
    gemm3_kernel<EPI_OUT>  <<<gg, 128, GEMM_SMEM>>>(dhi, dlo, whi + 5 * WW, wlo + 5 * WW, in_b + 2048, vbuf, nullptr, nullptr);

    // attention -> bf16 hi/lo split directly
    attn_kernel<<<Bb * H, 256, ATTN_SMEM>>>(qbuf, kbuf, vbuf, mask, ahi, alo);

    // mha_out projection with fused bias + split
    gemm3_kernel<EPI_SPLIT><<<gg, 128, GEMM_SMEM>>>(ahi, alo, whi + 6 * WW, wlo + 6 * WW, mo_b, nullptr, bhi, blo);

    // final projection with fused bias -> d_out
    gemm3_kernel<EPI_OUT>  <<<gg, 128, GEMM_SMEM>>>(bhi, blo, whi + 7LL * WW, wlo + 7LL * WW, o_b, out, nullptr, nullptr);
}